// round 1
// baseline (speedup 1.0000x reference)
#include <cuda_runtime.h>
#include <cuda_bf16.h>

// Problem constants
#define BATCH 8
#define CDIM 512
#define TDIM 1024
#define NGROUPS 32
#define GCH 16        // channels per group
#define NHEADS 8
#define CH 64         // head dim

// Scratch (allocation-free rule: __device__ globals)
__device__ float g_h[BATCH * CDIM * TDIM];          // 16 MB  groupnorm output
__device__ float g_qkv[BATCH * 3 * CDIM * TDIM];    // 48 MB  qkv projection
__device__ float g_a[BATCH * CDIM * TDIM];          // 16 MB  attention output

// ---------------------------------------------------------------------------
// GroupNorm: one block per (batch, group); 16 ch x 1024 t = 16384 elems
// ---------------------------------------------------------------------------
__global__ void groupnorm_kernel(const float* __restrict__ x,
                                 const float* __restrict__ gamma,
                                 const float* __restrict__ beta,
                                 float* __restrict__ out) {
    int b = blockIdx.x / NGROUPS;
    int g = blockIdx.x % NGROUPS;
    const float* xp = x + ((size_t)b * CDIM + g * GCH) * TDIM;
    const float4* x4 = (const float4*)xp;
    float s = 0.f, ss = 0.f;
    for (int i = threadIdx.x; i < GCH * TDIM / 4; i += blockDim.x) {
        float4 v = x4[i];
        s  += v.x + v.y + v.z + v.w;
        ss += v.x * v.x + v.y * v.y + v.z * v.z + v.w * v.w;
    }
    __shared__ float rs[256], rss[256];
    rs[threadIdx.x] = s; rss[threadIdx.x] = ss;
    __syncthreads();
    for (int st = 128; st > 0; st >>= 1) {
        if (threadIdx.x < st) {
            rs[threadIdx.x]  += rs[threadIdx.x + st];
            rss[threadIdx.x] += rss[threadIdx.x + st];
        }
        __syncthreads();
    }
    const float invn = 1.f / (GCH * TDIM);
    float mean = rs[0] * invn;
    float var  = rss[0] * invn - mean * mean;
    float rstd = rsqrtf(var + 1e-5f);
    float* op = out + ((size_t)b * CDIM + g * GCH) * TDIM;
    float4* o4 = (float4*)op;
    for (int i = threadIdx.x; i < GCH * TDIM / 4; i += blockDim.x) {
        int c = g * GCH + (i * 4) / TDIM;   // 4 elems always same channel (TDIM%4==0)
        float ga = gamma[c], be = beta[c];
        float4 v = x4[i];
        v.x = (v.x - mean) * rstd * ga + be;
        v.y = (v.y - mean) * rstd * ga + be;
        v.z = (v.z - mean) * rstd * ga + be;
        v.w = (v.w - mean) * rstd * ga + be;
        o4[i] = v;
    }
}

// ---------------------------------------------------------------------------
// Batched GEMM: C[b][m][t] = bias[m] + sum_k W[m][k] * H[b][k][t]  (+resid)
// block = 64(M) x 64(N) tile, 256 threads, 4x4 per thread, K tile = 16
// ---------------------------------------------------------------------------
template<int RESID>
__global__ void gemm_kernel(const float* __restrict__ W,
                            const float* __restrict__ Hm,
                            const float* __restrict__ bias,
                            const float* __restrict__ resid,
                            float* __restrict__ Cm,
                            int M, int K) {
    int b  = blockIdx.z;
    int m0 = blockIdx.x * 64;
    int n0 = blockIdx.y * 64;
    __shared__ float Ws[16][68];   // [k][m], padded
    __shared__ float Hs[16][68];   // [k][n], padded
    int ty = threadIdx.x >> 4;     // 0..15
    int tx = threadIdx.x & 15;     // 0..15
    float acc[4][4] = {};
    const float* Hb = Hm + (size_t)b * K * TDIM;

    int lrow = threadIdx.x >> 2;          // 0..63   (W tile row)
    int lk4  = (threadIdx.x & 3) * 4;     // 0..12   (W tile k chunk)
    int hrow = threadIdx.x >> 4;          // 0..15   (H tile row)
    int hc4  = (threadIdx.x & 15) * 4;    // 0..60   (H tile col chunk)

    for (int k0 = 0; k0 < K; k0 += 16) {
        float4 wv = *(const float4*)&W[(size_t)(m0 + lrow) * K + k0 + lk4];
        Ws[lk4 + 0][lrow] = wv.x;
        Ws[lk4 + 1][lrow] = wv.y;
        Ws[lk4 + 2][lrow] = wv.z;
        Ws[lk4 + 3][lrow] = wv.w;
        *(float4*)&Hs[hrow][hc4] =
            *(const float4*)&Hb[(size_t)(k0 + hrow) * TDIM + n0 + hc4];
        __syncthreads();
        #pragma unroll
        for (int kk = 0; kk < 16; kk++) {
            float4 a4 = *(const float4*)&Ws[kk][ty * 4];
            float4 b4 = *(const float4*)&Hs[kk][tx * 4];
            float av[4] = {a4.x, a4.y, a4.z, a4.w};
            float bv[4] = {b4.x, b4.y, b4.z, b4.w};
            #pragma unroll
            for (int i = 0; i < 4; i++)
                #pragma unroll
                for (int j = 0; j < 4; j++)
                    acc[i][j] = fmaf(av[i], bv[j], acc[i][j]);
        }
        __syncthreads();
    }

    #pragma unroll
    for (int i = 0; i < 4; i++) {
        int m = m0 + ty * 4 + i;
        float bi = bias[m];
        size_t off = ((size_t)b * M + m) * TDIM + n0 + tx * 4;
        float4 r;
        r.x = acc[i][0] + bi;
        r.y = acc[i][1] + bi;
        r.z = acc[i][2] + bi;
        r.w = acc[i][3] + bi;
        if (RESID) {
            float4 xr = *(const float4*)&resid[off];
            r.x += xr.x; r.y += xr.y; r.z += xr.z; r.w += xr.w;
        }
        *(float4*)&Cm[off] = r;
    }
}

// ---------------------------------------------------------------------------
// Flash attention: one block = one 64-query tile of one (batch, head).
// qkv layout per (b,head): channels [0,64)=q, [64,128)=k, [128,192)=v
// ---------------------------------------------------------------------------
struct AttnSmem {
    float Qs[64][64];    // [c][t], scale^2 folded in
    float Ks[64][68];    // [c][s]
    float Vs[64][68];    // [s][c] (transposed)
    float Ps[64][68];    // scores / probs [t][s]; reused as [c][t] for output
    float m_arr[64];
    float l_arr[64];
    float alpha_arr[64];
};

__global__ void attn_kernel(const float* __restrict__ qkv,
                            float* __restrict__ aout) {
    extern __shared__ char smem_raw[];
    AttnSmem& S = *reinterpret_cast<AttnSmem*>(smem_raw);

    int t0 = blockIdx.x * 64;
    int bh = blockIdx.y;
    int b = bh >> 3, h = bh & 7;
    const float* base = qkv + ((size_t)b * (3 * CDIM) + h * (3 * CH)) * TDIM;
    const float* qp = base;
    const float* kp = base + (size_t)CH * TDIM;
    const float* vp = base + (size_t)2 * CH * TDIM;

    int tid  = threadIdx.x;
    int lrow = tid >> 4;          // 0..15
    int lc4  = (tid & 15) * 4;    // 0..60
    int ty = tid >> 4, tx = tid & 15;

    const float scale2 = 0.125f;  // (1/ch^{1/4})^2 = 1/sqrt(64)
    #pragma unroll
    for (int r = 0; r < 4; r++) {
        int c = lrow + 16 * r;
        float4 v = *(const float4*)&qp[(size_t)c * TDIM + t0 + lc4];
        v.x *= scale2; v.y *= scale2; v.z *= scale2; v.w *= scale2;
        *(float4*)&S.Qs[c][lc4] = v;
    }
    if (tid < 64) { S.m_arr[tid] = -1e30f; S.l_arr[tid] = 0.f; }
    float O[4][4] = {};
    __syncthreads();

    for (int s0 = 0; s0 < TDIM; s0 += 64) {
        // load K [c][s] and V transposed [s][c]
        #pragma unroll
        for (int r = 0; r < 4; r++) {
            int c = lrow + 16 * r;
            *(float4*)&S.Ks[c][lc4] =
                *(const float4*)&kp[(size_t)c * TDIM + s0 + lc4];
            float4 vv = *(const float4*)&vp[(size_t)c * TDIM + s0 + lc4];
            S.Vs[lc4 + 0][c] = vv.x;
            S.Vs[lc4 + 1][c] = vv.y;
            S.Vs[lc4 + 2][c] = vv.z;
            S.Vs[lc4 + 3][c] = vv.w;
        }
        __syncthreads();

        // scores: S[t][s] = sum_c Qs[c][t]*Ks[c][s]
        float sc[4][4] = {};
        #pragma unroll
        for (int c = 0; c < 64; c++) {
            float4 q4 = *(const float4*)&S.Qs[c][ty * 4];
            float4 k4 = *(const float4*)&S.Ks[c][tx * 4];
            float qv[4] = {q4.x, q4.y, q4.z, q4.w};
            float kv[4] = {k4.x, k4.y, k4.z, k4.w};
            #pragma unroll
            for (int i = 0; i < 4; i++)
                #pragma unroll
                for (int j = 0; j < 4; j++)
                    sc[i][j] = fmaf(qv[i], kv[j], sc[i][j]);
        }
        #pragma unroll
        for (int i = 0; i < 4; i++) {
            float4 r4; r4.x = sc[i][0]; r4.y = sc[i][1]; r4.z = sc[i][2]; r4.w = sc[i][3];
            *(float4*)&S.Ps[ty * 4 + i][tx * 4] = r4;
        }
        __syncthreads();

        // online softmax: 4 lanes per row (lanes contiguous in warp)
        {
            int r = tid >> 2, sub = tid & 3;
            float mx = -1e30f;
            #pragma unroll
            for (int k = 0; k < 16; k++)
                mx = fmaxf(mx, S.Ps[r][sub * 16 + k]);
            mx = fmaxf(mx, __shfl_xor_sync(0xffffffffu, mx, 1));
            mx = fmaxf(mx, __shfl_xor_sync(0xffffffffu, mx, 2));
            float mold = S.m_arr[r];
            float mnew = fmaxf(mold, mx);
            float sum = 0.f;
            #pragma unroll
            for (int k = 0; k < 16; k++) {
                float p = __expf(S.Ps[r][sub * 16 + k] - mnew);
                S.Ps[r][sub * 16 + k] = p;
                sum += p;
            }
            sum += __shfl_xor_sync(0xffffffffu, sum, 1);
            sum += __shfl_xor_sync(0xffffffffu, sum, 2);
            float alpha = __expf(mold - mnew);
            if (sub == 0) {
                S.m_arr[r] = mnew;
                S.l_arr[r] = S.l_arr[r] * alpha + sum;
                S.alpha_arr[r] = alpha;
            }
        }
        __syncthreads();

        // O[t][c] = O*alpha + P @ V^T
        float al[4];
        #pragma unroll
        for (int i = 0; i < 4; i++) al[i] = S.alpha_arr[ty * 4 + i];
        #pragma unroll
        for (int i = 0; i < 4; i++)
            #pragma unroll
            for (int j = 0; j < 4; j++)
                O[i][j] *= al[i];
        #pragma unroll
        for (int s = 0; s < 64; s++) {
            float p0 = S.Ps[ty * 4 + 0][s];
            float p1 = S.Ps[ty * 4 + 1][s];
            float p2 = S.Ps[ty * 4 + 2][s];
            float p3 = S.Ps[ty * 4 + 3][s];
            float4 v4 = *(const float4*)&S.Vs[s][tx * 4];
            float vv[4] = {v4.x, v4.y, v4.z, v4.w};
            #pragma unroll
            for (int j = 0; j < 4; j++) {
                O[0][j] = fmaf(p0, vv[j], O[0][j]);
                O[1][j] = fmaf(p1, vv[j], O[1][j]);
                O[2][j] = fmaf(p2, vv[j], O[2][j]);
                O[3][j] = fmaf(p3, vv[j], O[3][j]);
            }
        }
        __syncthreads();
    }

    // normalize + transpose through smem, write [c][t] coalesced
    float inv[4];
    #pragma unroll
    for (int i = 0; i < 4; i++) inv[i] = 1.f / S.l_arr[ty * 4 + i];
    #pragma unroll
    for (int i = 0; i < 4; i++)
        #pragma unroll
        for (int j = 0; j < 4; j++)
            S.Ps[tx * 4 + j][ty * 4 + i] = O[i][j] * inv[i];  // Ps now [c][t]
    __syncthreads();
    {
        int c = tid >> 2, sub = tid & 3;
        size_t rowoff = ((size_t)b * CDIM + h * CH + c) * TDIM + t0;
        #pragma unroll
        for (int k4 = 0; k4 < 4; k4++) {
            float4 v = *(const float4*)&S.Ps[c][sub * 16 + k4 * 4];
            *(float4*)&aout[rowoff + sub * 16 + k4 * 4] = v;
        }
    }
}

// ---------------------------------------------------------------------------
extern "C" void kernel_launch(void* const* d_in, const int* in_sizes, int n_in,
                              void* d_out, int out_size) {
    const float* x      = (const float*)d_in[0];
    const float* gamma  = (const float*)d_in[1];
    const float* beta   = (const float*)d_in[2];
    const float* w_qkv  = (const float*)d_in[3];
    const float* b_qkv  = (const float*)d_in[4];
    const float* w_proj = (const float*)d_in[5];
    const float* b_proj = (const float*)d_in[6];
    float* out = (float*)d_out;

    float *hp, *qkvp, *ap;
    cudaGetSymbolAddress((void**)&hp,   g_h);
    cudaGetSymbolAddress((void**)&qkvp, g_qkv);
    cudaGetSymbolAddress((void**)&ap,   g_a);

    // 1) GroupNorm
    groupnorm_kernel<<<BATCH * NGROUPS, 256>>>(x, gamma, beta, hp);

    // 2) QKV projection: M=1536, K=512
    gemm_kernel<0><<<dim3(1536 / 64, TDIM / 64, BATCH), 256>>>(
        w_qkv, hp, b_qkv, nullptr, qkvp, 3 * CDIM, CDIM);

    // 3) Flash attention
    size_t attn_smem = sizeof(AttnSmem);
    cudaFuncSetAttribute(attn_kernel,
                         cudaFuncAttributeMaxDynamicSharedMemorySize,
                         (int)attn_smem);
    attn_kernel<<<dim3(TDIM / 64, BATCH * NHEADS), 256, attn_smem>>>(qkvp, ap);

    // 4) Output projection + residual: M=512, K=512
    gemm_kernel<1><<<dim3(CDIM / 64, TDIM / 64, BATCH), 256>>>(
        w_proj, ap, b_proj, x, out, CDIM, CDIM);
}

// round 4
// speedup vs baseline: 1.0457x; 1.0457x over previous
#include <cuda_runtime.h>
#include <cuda_bf16.h>

// Problem constants
#define BATCH 8
#define CDIM 512
#define TDIM 1024
#define NGROUPS 32
#define GCH 16        // channels per group
#define NHEADS 8
#define CH 64         // head dim

// Scratch (allocation-free rule: __device__ globals)
__device__ float g_h[BATCH * CDIM * TDIM];          // 16 MB  groupnorm output
__device__ float g_qkv[BATCH * 3 * CDIM * TDIM];    // 48 MB  qkv projection
__device__ float g_a[BATCH * CDIM * TDIM];          // 16 MB  attention output

// ---------------------------------------------------------------------------
// GroupNorm: one block per (batch, group); 16 ch x 1024 t = 16384 elems
// ---------------------------------------------------------------------------
__global__ void groupnorm_kernel(const float* __restrict__ x,
                                 const float* __restrict__ gamma,
                                 const float* __restrict__ beta,
                                 float* __restrict__ out) {
    int b = blockIdx.x / NGROUPS;
    int g = blockIdx.x % NGROUPS;
    const float* xp = x + ((size_t)b * CDIM + g * GCH) * TDIM;
    const float4* x4 = (const float4*)xp;
    float s = 0.f, ss = 0.f;
    for (int i = threadIdx.x; i < GCH * TDIM / 4; i += blockDim.x) {
        float4 v = x4[i];
        s  += v.x + v.y + v.z + v.w;
        ss += v.x * v.x + v.y * v.y + v.z * v.z + v.w * v.w;
    }
    __shared__ float rs[256], rss[256];
    rs[threadIdx.x] = s; rss[threadIdx.x] = ss;
    __syncthreads();
    for (int st = 128; st > 0; st >>= 1) {
        if (threadIdx.x < st) {
            rs[threadIdx.x]  += rs[threadIdx.x + st];
            rss[threadIdx.x] += rss[threadIdx.x + st];
        }
        __syncthreads();
    }
    const float invn = 1.f / (GCH * TDIM);
    float mean = rs[0] * invn;
    float var  = rss[0] * invn - mean * mean;
    float rstd = rsqrtf(var + 1e-5f);
    float* op = out + ((size_t)b * CDIM + g * GCH) * TDIM;
    float4* o4 = (float4*)op;
    for (int i = threadIdx.x; i < GCH * TDIM / 4; i += blockDim.x) {
        int c = g * GCH + (i * 4) / TDIM;
        float ga = gamma[c], be = beta[c];
        float4 v = x4[i];
        v.x = (v.x - mean) * rstd * ga + be;
        v.y = (v.y - mean) * rstd * ga + be;
        v.z = (v.z - mean) * rstd * ga + be;
        v.w = (v.w - mean) * rstd * ga + be;
        o4[i] = v;
    }
}

// ---------------------------------------------------------------------------
// Batched GEMM: C[b][m][t] = bias[m] + sum_k W[m][k] * H[b][k][t]  (+resid)
// 128x128 tile, K-tile 16, 256 threads, 8x8 per thread (split 4+4 at +64)
// ---------------------------------------------------------------------------
template<int RESID>
__global__ void __launch_bounds__(256, 2)
gemm_kernel(const float* __restrict__ W,
            const float* __restrict__ Hm,
            const float* __restrict__ bias,
            const float* __restrict__ resid,
            float* __restrict__ Cm,
            int M, int K) {
    __shared__ float Ws[16][128];   // [k][m]
    __shared__ float Hs[16][128];   // [k][n]
    int b  = blockIdx.z;
    int m0 = blockIdx.x * 128;
    int n0 = blockIdx.y * 128;
    int tid = threadIdx.x;
    int ty = tid >> 4;            // 0..15
    int tx = tid & 15;            // 0..15
    const float* Hb = Hm + (size_t)b * K * TDIM;

    int wr = tid >> 1;            // 0..127  W tile row
    int wk = (tid & 1) * 8;       // k chunk 0/8
    int hr = tid >> 4;            // 0..15   H tile k-row
    int hc = (tid & 15) * 8;      // col chunk

    float acc[8][8] = {};

    for (int k0 = 0; k0 < K; k0 += 16) {
        float4 w0 = *(const float4*)&W[(size_t)(m0 + wr) * K + k0 + wk];
        float4 w1 = *(const float4*)&W[(size_t)(m0 + wr) * K + k0 + wk + 4];
        float4 h0 = *(const float4*)&Hb[(size_t)(k0 + hr) * TDIM + n0 + hc];
        float4 h1 = *(const float4*)&Hb[(size_t)(k0 + hr) * TDIM + n0 + hc + 4];
        Ws[wk + 0][wr] = w0.x; Ws[wk + 1][wr] = w0.y;
        Ws[wk + 2][wr] = w0.z; Ws[wk + 3][wr] = w0.w;
        Ws[wk + 4][wr] = w1.x; Ws[wk + 5][wr] = w1.y;
        Ws[wk + 6][wr] = w1.z; Ws[wk + 7][wr] = w1.w;
        *(float4*)&Hs[hr][hc]     = h0;
        *(float4*)&Hs[hr][hc + 4] = h1;
        __syncthreads();
        #pragma unroll
        for (int kk = 0; kk < 16; kk++) {
            float a[8], bb[8];
            *(float4*)(a)      = *(const float4*)&Ws[kk][ty * 4];
            *(float4*)(a + 4)  = *(const float4*)&Ws[kk][64 + ty * 4];
            *(float4*)(bb)     = *(const float4*)&Hs[kk][tx * 4];
            *(float4*)(bb + 4) = *(const float4*)&Hs[kk][64 + tx * 4];
            #pragma unroll
            for (int i = 0; i < 8; i++)
                #pragma unroll
                for (int j = 0; j < 8; j++)
                    acc[i][j] = fmaf(a[i], bb[j], acc[i][j]);
        }
        __syncthreads();
    }

    #pragma unroll
    for (int i = 0; i < 8; i++) {
        int m = m0 + ((i < 4) ? (ty * 4 + i) : (64 + ty * 4 + i - 4));
        float bi = bias[m];
        #pragma unroll
        for (int jh = 0; jh < 2; jh++) {
            int n = n0 + ((jh == 0) ? (tx * 4) : (64 + tx * 4));
            size_t off = ((size_t)b * M + m) * TDIM + n;
            float4 r;
            r.x = acc[i][jh * 4 + 0] + bi;
            r.y = acc[i][jh * 4 + 1] + bi;
            r.z = acc[i][jh * 4 + 2] + bi;
            r.w = acc[i][jh * 4 + 3] + bi;
            if (RESID) {
                float4 xr = *(const float4*)&resid[off];
                r.x += xr.x; r.y += xr.y; r.z += xr.z; r.w += xr.w;
            }
            *(float4*)&Cm[off] = r;
        }
    }
}

// ---------------------------------------------------------------------------
// Flash attention: 128-query tile per block, 64-key steps, 256 threads.
// Scores kept in registers; softmax via half-warp shuffles; P through smem
// once (needed for P@V). qkv per (b,head): [0,64)=q, [64,128)=k, [128,192)=v
// ---------------------------------------------------------------------------
#define TQ 128
#define QS_STRIDE 132
#define KS_STRIDE 68
#define PS_FLOATS (128 * 68)

__global__ void __launch_bounds__(256)
attn_kernel(const float* __restrict__ qkv, float* __restrict__ aout) {
    extern __shared__ float sm[];
    float* Qs  = sm;                         // [64][132]  (c x t, scale^2 folded)
    float* Ks  = Qs + 64 * QS_STRIDE;        // [64][68]   (c x s)
    float* Vs  = Ks + 64 * KS_STRIDE;        // [64][68]   (s x c)
    float* Ps  = Vs + 64 * KS_STRIDE;        // 8704 floats: [128][68] / [64][132]
    float* m_s = Ps + PS_FLOATS;             // [128]
    float* l_s = m_s + 128;                  // [128]

    int t0 = blockIdx.x * TQ;
    int bh = blockIdx.y;
    int b = bh >> 3, h = bh & 7;
    const float* base = qkv + ((size_t)b * (3 * CDIM) + h * (3 * CH)) * TDIM;
    const float* qp = base;
    const float* kp = base + (size_t)CH * TDIM;
    const float* vp = base + (size_t)2 * CH * TDIM;

    int tid = threadIdx.x;
    int ty = tid >> 4, tx = tid & 15;

    // Load Q (scale^2 = 1/sqrt(64) folded in)
    {
        const float scale2 = 0.125f;
        int c = tid >> 2;                // 0..63
        int toff = (tid & 3) * 32;       // 0,32,64,96
        const float* qrow = qp + (size_t)c * TDIM + t0 + toff;
        float* qdst = Qs + c * QS_STRIDE + toff;
        #pragma unroll
        for (int u = 0; u < 8; u++) {
            float4 v = *(const float4*)&qrow[u * 4];
            v.x *= scale2; v.y *= scale2; v.z *= scale2; v.w *= scale2;
            *(float4*)&qdst[u * 4] = v;
        }
    }
    if (tid < 128) { m_s[tid] = -1e30f; l_s[tid] = 0.f; }

    float O[8][4] = {};

    for (int s0 = 0; s0 < TDIM; s0 += 64) {
        __syncthreads();   // protect K/V from previous iteration's readers
        // Load K [c][s] and V transposed [s][c]
        {
            int c = tid >> 2;            // 0..63
            int off = (tid & 3) * 16;    // s sub-range
            const float* krow = kp + (size_t)c * TDIM + s0 + off;
            const float* vrow = vp + (size_t)c * TDIM + s0 + off;
            float* kdst = Ks + c * KS_STRIDE + off;
            #pragma unroll
            for (int u = 0; u < 4; u++) {
                *(float4*)&kdst[u * 4] = *(const float4*)&krow[u * 4];
                float4 vv = *(const float4*)&vrow[u * 4];
                Vs[(off + u * 4 + 0) * KS_STRIDE + c] = vv.x;
                Vs[(off + u * 4 + 1) * KS_STRIDE + c] = vv.y;
                Vs[(off + u * 4 + 2) * KS_STRIDE + c] = vv.z;
                Vs[(off + u * 4 + 3) * KS_STRIDE + c] = vv.w;
            }
        }
        __syncthreads();

        // Scores in registers: sc[i][j], rows t = ty*4+i / 64+ty*4+(i-4),
        // cols s = s0 + tx*4+j
        float sc[8][4] = {};
        #pragma unroll 8
        for (int c = 0; c < 64; c++) {
            float a[8];
            *(float4*)(a)     = *(const float4*)&Qs[c * QS_STRIDE + ty * 4];
            *(float4*)(a + 4) = *(const float4*)&Qs[c * QS_STRIDE + 64 + ty * 4];
            float4 k4 = *(const float4*)&Ks[c * KS_STRIDE + tx * 4];
            float kv[4] = {k4.x, k4.y, k4.z, k4.w};
            #pragma unroll
            for (int i = 0; i < 8; i++)
                #pragma unroll
                for (int j = 0; j < 4; j++)
                    sc[i][j] = fmaf(a[i], kv[j], sc[i][j]);
        }

        // Online softmax per row (16 lanes of a half-warp own one row set)
        #pragma unroll
        for (int i = 0; i < 8; i++) {
            int row = (i < 4) ? (ty * 4 + i) : (64 + ty * 4 + i - 4);
            float mx = fmaxf(fmaxf(sc[i][0], sc[i][1]), fmaxf(sc[i][2], sc[i][3]));
            mx = fmaxf(mx, __shfl_xor_sync(0xffffffffu, mx, 1));
            mx = fmaxf(mx, __shfl_xor_sync(0xffffffffu, mx, 2));
            mx = fmaxf(mx, __shfl_xor_sync(0xffffffffu, mx, 4));
            mx = fmaxf(mx, __shfl_xor_sync(0xffffffffu, mx, 8));
            float mold = m_s[row];                 // warp-local: safe pre-write read
            float mnew = fmaxf(mold, mx);
            float p0 = __expf(sc[i][0] - mnew);
            float p1 = __expf(sc[i][1] - mnew);
            float p2 = __expf(sc[i][2] - mnew);
            float p3 = __expf(sc[i][3] - mnew);
            float sum = p0 + p1 + p2 + p3;
            sum += __shfl_xor_sync(0xffffffffu, sum, 1);
            sum += __shfl_xor_sync(0xffffffffu, sum, 2);
            sum += __shfl_xor_sync(0xffffffffu, sum, 4);
            sum += __shfl_xor_sync(0xffffffffu, sum, 8);
            float alpha = __expf(mold - mnew);
            if (tx == 0) {
                m_s[row] = mnew;
                l_s[row] = l_s[row] * alpha + sum;
            }
            *(float4*)&Ps[row * KS_STRIDE + tx * 4] = make_float4(p0, p1, p2, p3);
            O[i][0] *= alpha; O[i][1] *= alpha; O[i][2] *= alpha; O[i][3] *= alpha;
        }
        // No __syncthreads needed here: each warp reads back only the P rows
        // its own lanes wrote (row groups are half-warp-local).

        // O[t][c] += P @ V^T   (c cols = tx*4..+3)
        #pragma unroll 4
        for (int s = 0; s < 64; s += 4) {
            float4 v0 = *(const float4*)&Vs[(s + 0) * KS_STRIDE + tx * 4];
            float4 v1 = *(const float4*)&Vs[(s + 1) * KS_STRIDE + tx * 4];
            float4 v2 = *(const float4*)&Vs[(s + 2) * KS_STRIDE + tx * 4];
            float4 v3 = *(const float4*)&Vs[(s + 3) * KS_STRIDE + tx * 4];
            #pragma unroll
            for (int i = 0; i < 8; i++) {
                int row = (i < 4) ? (ty * 4 + i) : (64 + ty * 4 + i - 4);
                float4 pv = *(const float4*)&Ps[row * KS_STRIDE + s];
                O[i][0] = fmaf(pv.x, v0.x, O[i][0]);
                O[i][1] = fmaf(pv.x, v0.y, O[i][1]);
                O[i][2] = fmaf(pv.x, v0.z, O[i][2]);
                O[i][3] = fmaf(pv.x, v0.w, O[i][3]);
                O[i][0] = fmaf(pv.y, v1.x, O[i][0]);
                O[i][1] = fmaf(pv.y, v1.y, O[i][1]);
                O[i][2] = fmaf(pv.y, v1.z, O[i][2]);
                O[i][3] = fmaf(pv.y, v1.w, O[i][3]);
                O[i][0] = fmaf(pv.z, v2.x, O[i][0]);
                O[i][1] = fmaf(pv.z, v2.y, O[i][1]);
                O[i][2] = fmaf(pv.z, v2.z, O[i][2]);
                O[i][3] = fmaf(pv.z, v2.w, O[i][3]);
                O[i][0] = fmaf(pv.w, v3.x, O[i][0]);
                O[i][1] = fmaf(pv.w, v3.y, O[i][1]);
                O[i][2] = fmaf(pv.w, v3.z, O[i][2]);
                O[i][3] = fmaf(pv.w, v3.w, O[i][3]);
            }
        }
    }
    __syncthreads();   // Ps reuse below crosses warps

    // Normalize + transpose through Ps viewed as [64 c][132 t], then write
    #pragma unroll
    for (int i = 0; i < 8; i++) {
        int row = (i < 4) ? (ty * 4 + i) : (64 + ty * 4 + i - 4);
        float inv = 1.f / l_s[row];
        #pragma unroll
        for (int j = 0; j < 4; j++)
            Ps[(tx * 4 + j) * QS_STRIDE + row] = O[i][j] * inv;
    }
    __syncthreads();
    {
        int c = tid >> 2;
        int toff = (tid & 3) * 32;
        size_t gbase = ((size_t)b * CDIM + h * CH + c) * TDIM + t0 + toff;
        const float* src = Ps + c * QS_STRIDE + toff;
        #pragma unroll
        for (int u = 0; u < 8; u++)
            *(float4*)&aout[gbase + u * 4] = *(const float4*)&src[u * 4];
    }
}

// ---------------------------------------------------------------------------
extern "C" void kernel_launch(void* const* d_in, const int* in_sizes, int n_in,
                              void* d_out, int out_size) {
    const float* x      = (const float*)d_in[0];
    const float* gamma  = (const float*)d_in[1];
    const float* beta   = (const float*)d_in[2];
    const float* w_qkv  = (const float*)d_in[3];
    const float* b_qkv  = (const float*)d_in[4];
    const float* w_proj = (const float*)d_in[5];
    const float* b_proj = (const float*)d_in[6];
    float* out = (float*)d_out;

    float *hp, *qkvp, *ap;
    cudaGetSymbolAddress((void**)&hp,   g_h);
    cudaGetSymbolAddress((void**)&qkvp, g_qkv);
    cudaGetSymbolAddress((void**)&ap,   g_a);

    // 1) GroupNorm
    groupnorm_kernel<<<BATCH * NGROUPS, 256>>>(x, gamma, beta, hp);

    // 2) QKV projection: M=1536, K=512
    gemm_kernel<0><<<dim3(1536 / 128, TDIM / 128, BATCH), 256>>>(
        w_qkv, hp, b_qkv, nullptr, qkvp, 3 * CDIM, CDIM);

    // 3) Flash attention
    int attn_smem = (64 * QS_STRIDE + 2 * 64 * KS_STRIDE + PS_FLOATS + 256)
                    * (int)sizeof(float);
    cudaFuncSetAttribute(attn_kernel,
                         cudaFuncAttributeMaxDynamicSharedMemorySize, attn_smem);
    attn_kernel<<<dim3(TDIM / TQ, BATCH * NHEADS), 256, attn_smem>>>(qkvp, ap);

    // 4) Output projection + residual: M=512, K=512
    gemm_kernel<1><<<dim3(CDIM / 128, TDIM / 128, BATCH), 256>>>(
        w_proj, ap, b_proj, x, out, CDIM, CDIM);
}

// round 8
// speedup vs baseline: 1.4823x; 1.4175x over previous
#include <cuda_runtime.h>
#include <cstdint>

// Problem constants
#define BATCH 8
#define CDIM 512
#define TDIM 1024
#define NGROUPS 32
#define GCH 16
#define NHEADS 8
#define CH 64

// Scratch (allocation-free rule: __device__ globals)
__device__ float g_h[BATCH * CDIM * TDIM];
__device__ float g_qkv[BATCH * 3 * CDIM * TDIM];
__device__ float g_a[BATCH * CDIM * TDIM];

// ---------------------------------------------------------------------------
// tf32 helpers
// ---------------------------------------------------------------------------
__device__ __forceinline__ uint32_t f2tf(float x) {
    uint32_t r;
    asm("cvt.rna.tf32.f32 %0, %1;" : "=r"(r) : "f"(x));
    return r;
}
__device__ __forceinline__ float f2tff(float x) { return __uint_as_float(f2tf(x)); }

// D += A(16x8 row) * B(8x8 col), tf32 inputs, fp32 accum
__device__ __forceinline__ void mma_tf32(float* c,
                                         uint32_t a0, uint32_t a1, uint32_t a2, uint32_t a3,
                                         uint32_t b0, uint32_t b1) {
    asm volatile(
        "mma.sync.aligned.m16n8k8.row.col.f32.tf32.tf32.f32 "
        "{%0,%1,%2,%3},{%4,%5,%6,%7},{%8,%9},{%0,%1,%2,%3};"
        : "+f"(c[0]), "+f"(c[1]), "+f"(c[2]), "+f"(c[3])
        : "r"(a0), "r"(a1), "r"(a2), "r"(a3), "r"(b0), "r"(b1));
}

// within an 8-wide k-chunk, position of k so that (k, k+4) are adjacent words
// perm(k) = (k&3)*2 + (k>>2)
__device__ __forceinline__ int kcol(int k) {
    return ((k >> 3) << 3) + (((k & 3) << 1) | ((k >> 2) & 1));
}

// ---------------------------------------------------------------------------
// GroupNorm (unchanged, fp32)
// ---------------------------------------------------------------------------
__global__ void groupnorm_kernel(const float* __restrict__ x,
                                 const float* __restrict__ gamma,
                                 const float* __restrict__ beta,
                                 float* __restrict__ out) {
    int b = blockIdx.x / NGROUPS;
    int g = blockIdx.x % NGROUPS;
    const float* xp = x + ((size_t)b * CDIM + g * GCH) * TDIM;
    const float4* x4 = (const float4*)xp;
    float s = 0.f, ss = 0.f;
    for (int i = threadIdx.x; i < GCH * TDIM / 4; i += blockDim.x) {
        float4 v = x4[i];
        s  += v.x + v.y + v.z + v.w;
        ss += v.x * v.x + v.y * v.y + v.z * v.z + v.w * v.w;
    }
    __shared__ float rs[256], rss[256];
    rs[threadIdx.x] = s; rss[threadIdx.x] = ss;
    __syncthreads();
    for (int st = 128; st > 0; st >>= 1) {
        if (threadIdx.x < st) {
            rs[threadIdx.x]  += rs[threadIdx.x + st];
            rss[threadIdx.x] += rss[threadIdx.x + st];
        }
        __syncthreads();
    }
    const float invn = 1.f / (GCH * TDIM);
    float mean = rs[0] * invn;
    float var  = rss[0] * invn - mean * mean;
    float rstd = rsqrtf(var + 1e-5f);
    float* op = out + ((size_t)b * CDIM + g * GCH) * TDIM;
    float4* o4 = (float4*)op;
    for (int i = threadIdx.x; i < GCH * TDIM / 4; i += blockDim.x) {
        int c = g * GCH + (i * 4) / TDIM;
        float ga = gamma[c], be = beta[c];
        float4 v = x4[i];
        v.x = (v.x - mean) * rstd * ga + be;
        v.y = (v.y - mean) * rstd * ga + be;
        v.z = (v.z - mean) * rstd * ga + be;
        v.w = (v.w - mean) * rstd * ga + be;
        o4[i] = v;
    }
}

// ---------------------------------------------------------------------------
// tf32 tensor-core batched GEMM: C[b][m][t] = bias[m] + W[m][:] . H[b][:][t]
// 128x128x32 block tile, 8 warps (2M x 4N), warp tile 64x32, m16n8k8 atoms
// Ws: [m][kperm] stride 34 (A-frag = LDS.64); Hs: [k][n] stride 132
// ---------------------------------------------------------------------------
#define WST 34
#define HST 132

template<int RESID>
__global__ void __launch_bounds__(256, 2)
gemm_tf32(const float* __restrict__ W, const float* __restrict__ Hm,
          const float* __restrict__ bias, const float* __restrict__ resid,
          float* __restrict__ Cm, int M, int K) {
    __shared__ float Ws[128 * WST];
    __shared__ float Hs[32 * HST];
    int b = blockIdx.z, m0 = blockIdx.x * 128, n0 = blockIdx.y * 128;
    int tid = threadIdx.x, lane = tid & 31, wid = tid >> 5;
    int wM = (wid >> 2) * 64, wN = (wid & 3) * 32;
    int g = lane >> 2, q = lane & 3;
    const float* Hb = Hm + (size_t)b * K * TDIM;
    float acc[4][4][4] = {};

    int wr = tid >> 1, wh = (tid & 1) * 2;   // W: row, chunk pair
    int hr = tid >> 4, hc = (tid & 15) * 8;  // H: k row, n chunk

    for (int k0 = 0; k0 < K; k0 += 32) {
        // W tile 128x32 -> Ws[m][kperm]
        #pragma unroll
        for (int p = 0; p < 2; p++) {
            int ch = wh + p, kk = ch * 8;
            const float* wp = &W[(size_t)(m0 + wr) * K + k0 + kk];
            float4 w0 = *(const float4*)wp;
            float4 w1 = *(const float4*)(wp + 4);
            float* dst = &Ws[wr * WST + kk];
            ((float2*)dst)[0] = make_float2(f2tff(w0.x), f2tff(w1.x));
            ((float2*)dst)[1] = make_float2(f2tff(w0.y), f2tff(w1.y));
            ((float2*)dst)[2] = make_float2(f2tff(w0.z), f2tff(w1.z));
            ((float2*)dst)[3] = make_float2(f2tff(w0.w), f2tff(w1.w));
        }
        // H tile 32x128 -> Hs[k][n] natural
        #pragma unroll
        for (int rr = 0; rr < 2; rr++) {
            int row = hr + 16 * rr;
            const float* hp = &Hb[(size_t)(k0 + row) * TDIM + n0 + hc];
            float4 h0 = *(const float4*)hp;
            float4 h1 = *(const float4*)(hp + 4);
            float* dst = &Hs[row * HST + hc];
            dst[0] = f2tff(h0.x); dst[1] = f2tff(h0.y);
            dst[2] = f2tff(h0.z); dst[3] = f2tff(h0.w);
            dst[4] = f2tff(h1.x); dst[5] = f2tff(h1.y);
            dst[6] = f2tff(h1.z); dst[7] = f2tff(h1.w);
        }
        __syncthreads();

        #pragma unroll
        for (int ch = 0; ch < 4; ch++) {
            int cb = ch * 8 + 2 * q;
            uint32_t af[4][4];
            #pragma unroll
            for (int i = 0; i < 4; i++) {
                int row = wM + 16 * i + g;
                uint2 au = *(const uint2*)&Ws[row * WST + cb];
                uint2 al = *(const uint2*)&Ws[(row + 8) * WST + cb];
                af[i][0] = au.x; af[i][1] = al.x; af[i][2] = au.y; af[i][3] = al.y;
            }
            #pragma unroll
            for (int j = 0; j < 4; j++) {
                int n = wN + 8 * j + g;
                uint32_t b0 = __float_as_uint(Hs[(ch * 8 + q) * HST + n]);
                uint32_t b1 = __float_as_uint(Hs[(ch * 8 + q + 4) * HST + n]);
                #pragma unroll
                for (int i = 0; i < 4; i++)
                    mma_tf32(acc[i][j], af[i][0], af[i][1], af[i][2], af[i][3], b0, b1);
            }
        }
        __syncthreads();
    }

    // epilogue: c-frag (row g/g+8, col 2q,2q+1) -> float2 global stores
    #pragma unroll
    for (int i = 0; i < 4; i++) {
        int mlo = m0 + wM + 16 * i + g;
        float blo = bias[mlo], bhi = bias[mlo + 8];
        #pragma unroll
        for (int j = 0; j < 4; j++) {
            int n = n0 + wN + 8 * j + 2 * q;
            size_t olo = ((size_t)b * M + mlo) * TDIM + n;
            size_t ohi = olo + (size_t)8 * TDIM;
            float2 lo = make_float2(acc[i][j][0] + blo, acc[i][j][1] + blo);
            float2 hi = make_float2(acc[i][j][2] + bhi, acc[i][j][3] + bhi);
            if (RESID) {
                float2 r0 = *(const float2*)&resid[olo];
                float2 r1 = *(const float2*)&resid[ohi];
                lo.x += r0.x; lo.y += r0.y; hi.x += r1.x; hi.y += r1.y;
            }
            *(float2*)&Cm[olo] = lo;
            *(float2*)&Cm[ohi] = hi;
        }
    }
}

// ---------------------------------------------------------------------------
// tf32 flash attention: block = 128 queries of one (b,head); 8 warps x 16 rows
// Qs [t][cperm] s66 | Ks [c][s] s68 | Vs [c][sperm] s66 | Ps [t][sperm] s66
// ---------------------------------------------------------------------------
#define AST 66
#define KST 68

__global__ void __launch_bounds__(256)
attn_tf32(const float* __restrict__ qkv, float* __restrict__ aout) {
    extern __shared__ float sm[];
    float* Qs = sm;                  // 128*66
    float* Ks = Qs + 128 * AST;      // 64*68
    float* Vs = Ks + 64 * KST;       // 64*66
    float* Ps = Vs + 64 * AST;       // 128*66  (reused as Os[64][132] at end)

    int t0 = blockIdx.x * 128;
    int bh = blockIdx.y;
    int b = bh >> 3, h = bh & 7;
    const float* base = qkv + ((size_t)b * (3 * CDIM) + h * (3 * CH)) * TDIM;
    const float* qp = base;
    const float* kp = base + (size_t)CH * TDIM;
    const float* vp = base + (size_t)2 * CH * TDIM;

    int tid = threadIdx.x, lane = tid & 31, wid = tid >> 5;
    int g = lane >> 2, q = lane & 3;
    int r0 = wid * 16 + g;           // this thread's query rows: r0, r0+8

    // Q: [c][t] global -> Qs[t][cperm]; scale 0.125 (exact pow2)
    {
        int cr = tid >> 4, tb = tid & 15;
        #pragma unroll
        for (int u2 = 0; u2 < 4; u2++) {
            int c = cr + 16 * u2;
            int col = kcol(c);
            const float* qrow = qp + (size_t)c * TDIM + t0;
            #pragma unroll
            for (int u = 0; u < 8; u++) {
                int t = tb + 16 * u;
                Qs[t * AST + col] = f2tff(qrow[t] * 0.125f);
            }
        }
    }

    float mr0 = -1e30f, mr1 = -1e30f, lr0 = 0.f, lr1 = 0.f;
    float O[8][4] = {};
    const int pc = (((2 * q) & 3) << 1) | ((q >> 1) & 1);   // perm(2q)

    for (int s0 = 0; s0 < TDIM; s0 += 64) {
        __syncthreads();
        // K [c][s] natural, V [c][sperm]
        {
            int c = tid >> 2, s4 = (tid & 3) * 16;
            const float* krow = kp + (size_t)c * TDIM + s0 + s4;
            float* kd = &Ks[c * KST + s4];
            #pragma unroll
            for (int u = 0; u < 4; u++) {
                float4 v = *(const float4*)&krow[4 * u];
                kd[4 * u + 0] = f2tff(v.x); kd[4 * u + 1] = f2tff(v.y);
                kd[4 * u + 2] = f2tff(v.z); kd[4 * u + 3] = f2tff(v.w);
            }
            const float* vrow = vp + (size_t)c * TDIM + s0 + s4;
            float4 v0 = *(const float4*)&vrow[0];
            float4 v1 = *(const float4*)&vrow[4];
            float4 v2 = *(const float4*)&vrow[8];
            float4 v3 = *(const float4*)&vrow[12];
            float* vd = &Vs[c * AST + s4];
            ((float2*)vd)[0] = make_float2(f2tff(v0.x), f2tff(v1.x));
            ((float2*)vd)[1] = make_float2(f2tff(v0.y), f2tff(v1.y));
            ((float2*)vd)[2] = make_float2(f2tff(v0.z), f2tff(v1.z));
            ((float2*)vd)[3] = make_float2(f2tff(v0.w), f2tff(v1.w));
            float* vd2 = vd + 8;
            ((float2*)vd2)[0] = make_float2(f2tff(v2.x), f2tff(v3.x));
            ((float2*)vd2)[1] = make_float2(f2tff(v2.y), f2tff(v3.y));
            ((float2*)vd2)[2] = make_float2(f2tff(v2.z), f2tff(v3.z));
            ((float2*)vd2)[3] = make_float2(f2tff(v2.w), f2tff(v3.w));
        }
        __syncthreads();

        // S = (Q*s) (K*s)^T : warp tile 16x64, k over c (8 chunks)
        float sc[8][4] = {};
        #pragma unroll
        for (int cc = 0; cc < 8; cc++) {
            int cb = cc * 8 + 2 * q;
            uint2 au = *(const uint2*)&Qs[r0 * AST + cb];
            uint2 al = *(const uint2*)&Qs[(r0 + 8) * AST + cb];
            #pragma unroll
            for (int j = 0; j < 8; j++) {
                int s = 8 * j + g;
                uint32_t b0 = __float_as_uint(Ks[(cc * 8 + q) * KST + s]);
                uint32_t b1 = __float_as_uint(Ks[(cc * 8 + q + 4) * KST + s]);
                mma_tf32(sc[j], au.x, al.x, au.y, al.y, b0, b1);
            }
        }

        // online softmax: row r0 holds sc[j][0..1], row r0+8 holds sc[j][2..3]
        float mx0 = -1e30f, mx1 = -1e30f;
        #pragma unroll
        for (int j = 0; j < 8; j++) {
            mx0 = fmaxf(mx0, fmaxf(sc[j][0], sc[j][1]));
            mx1 = fmaxf(mx1, fmaxf(sc[j][2], sc[j][3]));
        }
        mx0 = fmaxf(mx0, __shfl_xor_sync(0xffffffffu, mx0, 1));
        mx0 = fmaxf(mx0, __shfl_xor_sync(0xffffffffu, mx0, 2));
        mx1 = fmaxf(mx1, __shfl_xor_sync(0xffffffffu, mx1, 1));
        mx1 = fmaxf(mx1, __shfl_xor_sync(0xffffffffu, mx1, 2));
        float mn0 = fmaxf(mr0, mx0), mn1 = fmaxf(mr1, mx1);
        float a0 = __expf(mr0 - mn0), a1 = __expf(mr1 - mn1);
        mr0 = mn0; mr1 = mn1;
        float sum0 = 0.f, sum1 = 0.f;
        #pragma unroll
        for (int j = 0; j < 8; j++) {
            float p0 = __expf(sc[j][0] - mn0);
            float p1 = __expf(sc[j][1] - mn0);
            float p2 = __expf(sc[j][2] - mn1);
            float p3 = __expf(sc[j][3] - mn1);
            sum0 += p0 + p1; sum1 += p2 + p3;
            int cb = 8 * j;
            Ps[r0 * AST + cb + pc]           = __uint_as_float(f2tf(p0));
            Ps[r0 * AST + cb + pc + 2]       = __uint_as_float(f2tf(p1));
            Ps[(r0 + 8) * AST + cb + pc]     = __uint_as_float(f2tf(p2));
            Ps[(r0 + 8) * AST + cb + pc + 2] = __uint_as_float(f2tf(p3));
            O[j][0] *= a0; O[j][1] *= a0; O[j][2] *= a1; O[j][3] *= a1;
        }
        sum0 += __shfl_xor_sync(0xffffffffu, sum0, 1);
        sum0 += __shfl_xor_sync(0xffffffffu, sum0, 2);
        sum1 += __shfl_xor_sync(0xffffffffu, sum1, 1);
        sum1 += __shfl_xor_sync(0xffffffffu, sum1, 2);
        lr0 = lr0 * a0 + sum0;
        lr1 = lr1 * a1 + sum1;
        __syncwarp();   // P rows are warp-private; order stores before A-frag loads

        // O += P V^T : warp tile 16x64, k over s (8 chunks)
        #pragma unroll
        for (int ch = 0; ch < 8; ch++) {
            int cb = ch * 8 + 2 * q;
            uint2 au = *(const uint2*)&Ps[r0 * AST + cb];
            uint2 al = *(const uint2*)&Ps[(r0 + 8) * AST + cb];
            #pragma unroll
            for (int j = 0; j < 8; j++) {
                uint2 bv = *(const uint2*)&Vs[(8 * j + g) * AST + cb];
                mma_tf32(O[j], au.x, al.x, au.y, al.y, bv.x, bv.y);
            }
        }
    }
    __syncthreads();   // everyone done with Ps before reuse as Os

    // normalize, transpose to Os[c][t] (reuse Ps: 128*66 == 64*132)
    float inv0 = 1.f / lr0, inv1 = 1.f / lr1;
    float* Os = Ps;
    #pragma unroll
    for (int j = 0; j < 8; j++) {
        int c = 8 * j + 2 * q;
        Os[c * 132 + r0]           = O[j][0] * inv0;
        Os[(c + 1) * 132 + r0]     = O[j][1] * inv0;
        Os[c * 132 + r0 + 8]       = O[j][2] * inv1;
        Os[(c + 1) * 132 + r0 + 8] = O[j][3] * inv1;
    }
    __syncthreads();
    {
        int c = tid >> 2, tb = (tid & 3) * 32;
        size_t gb = ((size_t)b * CDIM + h * CH + c) * TDIM + t0 + tb;
        const float* src = &Os[c * 132 + tb];
        #pragma unroll
        for (int u = 0; u < 8; u++)
            *(float4*)&aout[gb + 4 * u] = *(const float4*)&src[4 * u];
    }
}

// ---------------------------------------------------------------------------
extern "C" void kernel_launch(void* const* d_in, const int* in_sizes, int n_in,
                              void* d_out, int out_size) {
    const float* x      = (const float*)d_in[0];
    const float* gamma  = (const float*)d_in[1];
    const float* beta   = (const float*)d_in[2];
    const float* w_qkv  = (const float*)d_in[3];
    const float* b_qkv  = (const float*)d_in[4];
    const float* w_proj = (const float*)d_in[5];
    const float* b_proj = (const float*)d_in[6];
    float* out = (float*)d_out;

    float *hp, *qkvp, *ap;
    cudaGetSymbolAddress((void**)&hp,   g_h);
    cudaGetSymbolAddress((void**)&qkvp, g_qkv);
    cudaGetSymbolAddress((void**)&ap,   g_a);

    // 1) GroupNorm
    groupnorm_kernel<<<BATCH * NGROUPS, 256>>>(x, gamma, beta, hp);

    // 2) QKV projection: M=1536, K=512 (tf32 tensor cores)
    gemm_tf32<0><<<dim3(12, 8, BATCH), 256>>>(
        w_qkv, hp, b_qkv, nullptr, qkvp, 3 * CDIM, CDIM);

    // 3) Flash attention (tf32 tensor cores)
    int attn_smem = (128 * AST + 64 * KST + 64 * AST + 128 * AST)
                    * (int)sizeof(float);
    cudaFuncSetAttribute(attn_tf32,
                         cudaFuncAttributeMaxDynamicSharedMemorySize, attn_smem);
    attn_tf32<<<dim3(TDIM / 128, BATCH * NHEADS), 256, attn_smem>>>(qkvp, ap);

    // 4) Output projection + residual: M=512, K=512 (tf32 tensor cores)
    gemm_tf32<1><<<dim3(4, 8, BATCH), 256>>>(
        w_proj, ap, b_proj, x, out, CDIM, CDIM);
}